// round 8
// baseline (speedup 1.0000x reference)
#include <cuda_runtime.h>
#include <cuda_fp16.h>
#include <cstdint>

// LoRAConv3d: out = conv3(x,[W;A]) -> (base+bias, low); out += 2*B@boxsum3(low)
// Implicit GEMM on mma.sync.m16n8k16 (f16 in, f32 acc).
// B=2, CIN=64, COUT=128, RANK=16, K=3^3, spatial 32^3, pad 1.

__device__ __half  xpad[2 * 34 * 34 * 34 * 64];   // padded NDHWC fp16
__device__ __half  wk[27 * 144 * 64];             // [off][n][c]
__device__ float   g_low[2 * 16 * 32768];

// ---------------- helpers ----------------
__device__ __forceinline__ uint32_t smem_u32(const void* p) {
    uint32_t a;
    asm("{ .reg .u64 t; cvta.to.shared.u64 t, %1; cvt.u32.u64 %0, t; }" : "=r"(a) : "l"(p));
    return a;
}
__device__ __forceinline__ void cp16(uint32_t dst, const void* src) {
    asm volatile("cp.async.cg.shared.global [%0], [%1], 16;" :: "r"(dst), "l"(src));
}
__device__ __forceinline__ void cp_commit() { asm volatile("cp.async.commit_group;"); }
template <int N> __device__ __forceinline__ void cp_wait() {
    asm volatile("cp.async.wait_group %0;" :: "n"(N) : "memory");
}
__device__ __forceinline__ void ldsm4(uint32_t* r, uint32_t addr) {
    asm volatile("ldmatrix.sync.aligned.m8n8.x4.shared.b16 {%0,%1,%2,%3}, [%4];"
                 : "=r"(r[0]), "=r"(r[1]), "=r"(r[2]), "=r"(r[3]) : "r"(addr));
}
__device__ __forceinline__ void ldsm2(uint32_t& b0, uint32_t& b1, uint32_t addr) {
    asm volatile("ldmatrix.sync.aligned.m8n8.x2.shared.b16 {%0,%1}, [%2];"
                 : "=r"(b0), "=r"(b1) : "r"(addr));
}
__device__ __forceinline__ void mma16816(float* c, const uint32_t* a,
                                         uint32_t b0, uint32_t b1) {
    asm volatile(
        "mma.sync.aligned.m16n8k16.row.col.f32.f16.f16.f32 "
        "{%0,%1,%2,%3}, {%4,%5,%6,%7}, {%8,%9}, {%0,%1,%2,%3};"
        : "+f"(c[0]), "+f"(c[1]), "+f"(c[2]), "+f"(c[3])
        : "r"(a[0]), "r"(a[1]), "r"(a[2]), "r"(a[3]), "r"(b0), "r"(b1));
}

// ---------------- prep: pad/transpose x ----------------
// one block per (b, zp): writes the whole 34y x 34x x 64c plane of xpad.
__global__ __launch_bounds__(256) void pad_x_kernel(const float* __restrict__ x) {
    int id = blockIdx.x;                       // 2*34
    int b = id / 34, zp = id - b * 34;
    const bool zin = (zp >= 1 && zp <= 32);
    __shared__ float s[32 * 73];               // [xx][c], stride 73 (conflict-free)

    for (int yp = 0; yp < 34; ++yp) {
        const bool interior = zin && yp >= 1 && yp <= 32;
        if (interior) {
            // load x[b, c, zp-1, yp-1, :]: 64c x 32x floats
            for (int i = threadIdx.x; i < 2048; i += 256) {
                int c = i >> 5, xx = i & 31;
                float v = x[((b * 64 + c) << 15) + ((zp - 1) << 10) + ((yp - 1) << 5) + xx];
                s[xx * 73 + c] = v;
            }
        }
        __syncthreads();
        uint2* dst = (uint2*)(xpad + (size_t)((b * 34 + zp) * 34 + yp) * 34 * 64);
        // 34*64 halves = 544 uint2 (4 halves each)
        for (int i = threadIdx.x; i < 544; i += 256) {
            int xi = i >> 4, c0 = (i & 15) << 2;
            uint2 o;
            if (interior && xi >= 1 && xi <= 32) {
                const float* sp = &s[(xi - 1) * 73 + c0];
                __half2 h0 = __floats2half2_rn(sp[0], sp[1]);
                __half2 h1 = __floats2half2_rn(sp[2], sp[3]);
                o.x = *(uint32_t*)&h0;
                o.y = *(uint32_t*)&h1;
            } else {
                o.x = 0u; o.y = 0u;
            }
            dst[i] = o;
        }
        __syncthreads();
    }
}

// one block per output channel n (144 blocks): coalesced read, contiguous write.
__global__ __launch_bounds__(224) void prep_w_kernel(
    const float* __restrict__ weight, const float* __restrict__ lora_A)
{
    __shared__ float s[1728];
    const int n = blockIdx.x;
    const float* src = (n < 128) ? (weight + (size_t)n * 1728)
                                 : (lora_A + (size_t)(n - 128) * 1728);
    for (int i = threadIdx.x; i < 432; i += 224)
        *(float4*)&s[i * 4] = *(const float4*)&src[i * 4];
    __syncthreads();
    // wk[off][n][c] = s[c*27 + off]; write 4 halves (c0..c0+3) per uint2
    for (int i = threadIdx.x; i < 432; i += 224) {
        int off = i >> 4, c0 = (i & 15) << 2;
        __half2 h0 = __floats2half2_rn(s[c0 * 27 + off], s[(c0 + 1) * 27 + off]);
        __half2 h1 = __floats2half2_rn(s[(c0 + 2) * 27 + off], s[(c0 + 3) * 27 + off]);
        uint2 o; o.x = *(uint32_t*)&h0; o.y = *(uint32_t*)&h1;
        *(uint2*)&wk[(size_t)off * 9216 + n * 64 + c0] = o;
    }
}

// ---------------- main conv: implicit GEMM on mma.sync (R6, unchanged) ----------------
// per CTA: M=128 positions (2z x 4y x 16x), N=144, 27 offsets (K=64 each).
#define SA_BYTES   (432 * 144)                 // 62208
#define SB_STRIDE  (144 * 144)                 // 20736
#define SB_OFF     SA_BYTES
#define SBIAS_OFF  (SA_BYTES + 2 * SB_STRIDE)  // 103680
#define SMEM_TOTAL (SBIAS_OFF + 512)           // 104192

__device__ __forceinline__ void stage_B(uint32_t buf, int off, int tid) {
    const char* wb = (const char*)wk + (size_t)off * 18432;
#pragma unroll
    for (int i = tid; i < 1152; i += 256) {
        int row = i >> 3, k = i & 7;
        cp16(buf + row * 144 + k * 16, wb + row * 128 + k * 16);
    }
}

__global__ __launch_bounds__(256, 2) void conv_mma_kernel(
    const float* __restrict__ bias, float* __restrict__ out)
{
    extern __shared__ char smem[];
    const uint32_t sb = smem_u32(smem);
    const uint32_t sA = sb, sB = sb + SB_OFF;
    float* sbias = (float*)(smem + SBIAS_OFF);

    const int tid = threadIdx.x, lane = tid & 31, wid = tid >> 5;
    const int t = blockIdx.x;                  // 512 tiles
    const int b  = t >> 8;
    const int r  = t & 255;
    const int z0 = (r >> 4) * 2;
    const int y0 = ((r >> 1) & 7) * 4;
    const int x0 = (r & 1) * 16;

    if (tid < 128) sbias[tid] = bias[tid];

    {
        const char* xb = (const char*)xpad;
        for (int i = tid; i < 3456; i += 256) {
            int rr = i >> 3, k = i & 7;
            int dz = rr / 108, rem = rr - dz * 108;
            int yi = rem / 18, xi = rem - yi * 18;
            size_t src = ((size_t)(((b * 34 + z0 + dz) * 34 + (y0 + yi)) * 34 + (x0 + xi)))
                         * 128 + k * 16;
            cp16(sA + rr * 144 + k * 16, xb + src);
        }
    }
    stage_B(sB, 0, tid);
    cp_commit();

    const int m0w = (wid >> 1) * 32;
    const int n0w = (wid & 1) * 72;
    uint32_t laneA[2];
#pragma unroll
    for (int mi = 0; mi < 2; ++mi) {
        int m = m0w + mi * 16 + (lane & 15);
        int zi = m >> 6, yi = (m >> 4) & 3, xi = m & 15;
        laneA[mi] = (uint32_t)((zi * 108 + yi * 18 + xi) * 144 + ((lane >> 4) << 4));
    }
    const uint32_t laneB4 =
        (uint32_t)((n0w + ((lane >> 4) & 1) * 8 + (lane & 7)) * 144
                   + ((lane >> 3) & 1) * 16);
    const uint32_t laneB2 =
        (uint32_t)((n0w + 64 + (lane & 7)) * 144 + ((lane >> 3) & 1) * 16);

    float acc[2][9][4];
#pragma unroll
    for (int mi = 0; mi < 2; ++mi)
#pragma unroll
        for (int nj = 0; nj < 9; ++nj)
#pragma unroll
            for (int q = 0; q < 4; ++q) acc[mi][nj][q] = 0.f;

    for (int off = 0; off < 27; ++off) {
        cp_wait<0>();
        __syncthreads();
        if (off < 26) {
            stage_B(sB + ((off + 1) & 1) * SB_STRIDE, off + 1, tid);
            cp_commit();
        }
        const int dz = off / 9, r9 = off - dz * 9;
        const int dy = r9 / 3, dx = r9 - dy * 3;
        const uint32_t aoff = sA + (uint32_t)((dz * 108 + dy * 18 + dx) * 144);
        const uint32_t bb   = sB + (off & 1) * SB_STRIDE;
        const uint32_t b4   = bb + laneB4;
        const uint32_t b2   = bb + laneB2;

#pragma unroll
        for (int s = 0; s < 4; ++s) {
            const uint32_t so = (uint32_t)(s * 32);
            uint32_t a0[4], a1[4];
            ldsm4(a0, aoff + laneA[0] + so);
            ldsm4(a1, aoff + laneA[1] + so);
            uint32_t bf[18];
#pragma unroll
            for (int p = 0; p < 4; ++p) ldsm4(&bf[p * 4], b4 + p * 2304 + so);
            ldsm2(bf[16], bf[17], b2 + so);
#pragma unroll
            for (int nj = 0; nj < 9; ++nj) {
                const uint32_t bv0 = (nj < 8) ? bf[(nj >> 1) * 4 + (nj & 1) * 2] : bf[16];
                const uint32_t bv1 = (nj < 8) ? bf[(nj >> 1) * 4 + (nj & 1) * 2 + 1] : bf[17];
                mma16816(acc[0][nj], a0, bv0, bv1);
                mma16816(acc[1][nj], a1, bv0, bv1);
            }
        }
    }

    // epilogue
#pragma unroll
    for (int mi = 0; mi < 2; ++mi) {
        const int r0 = m0w + mi * 16 + (lane >> 2);
        const int r1 = r0 + 8;
        const int pos0 = (z0 + (r0 >> 6)) * 1024 + (y0 + ((r0 >> 4) & 3)) * 32
                         + x0 + (r0 & 15);
        const int pos1 = (z0 + (r1 >> 6)) * 1024 + (y0 + ((r1 >> 4) & 3)) * 32
                         + x0 + (r1 & 15);
#pragma unroll
        for (int nj = 0; nj < 9; ++nj) {
            const int c0 = n0w + nj * 8 + ((lane & 3) << 1);
#pragma unroll
            for (int q = 0; q < 4; ++q) {
                const int c = c0 + (q & 1);
                const int pos = (q < 2) ? pos0 : pos1;
                const float v = acc[mi][nj][q];
                if (c < 128)
                    out[(size_t)(b * 128 + c) * 32768 + pos] = v + sbias[c];
                else
                    g_low[(size_t)(b * 16 + (c - 128)) * 32768 + pos] = v;
            }
        }
    }
}

// ---------------- fused boxsum + lora apply (float4) ----------------
// block per (b, z, group-of-32-oc): 256 threads, each owns 4 consecutive x.
#define LORA_SMEM (16 * 1024 * 4 + 512 * 4)    // 67584
__global__ __launch_bounds__(256) void lora_fused_kernel(
    const float* __restrict__ lora_B, float* __restrict__ out)
{
    extern __shared__ float lsm[];
    float* zsum = lsm;                 // [16][1024]
    float* sB2  = lsm + 16 * 1024;     // [32][16], pre-scaled by 2

    const int id = blockIdx.x;         // 256 blocks: b*128 + z*4 + g
    const int g = id & 3, z = (id >> 2) & 31, b = id >> 7;
    const int tid = threadIdx.x;
    const int p0 = tid << 2;           // base position in plane (4 | p0)
    const int y = p0 >> 5, x0 = p0 & 31;

    for (int i = tid; i < 512; i += 256) sB2[i] = 2.0f * lora_B[g * 512 + i];

    // z-sum (float4)
#pragma unroll
    for (int r = 0; r < 16; ++r) {
        const float* base = g_low + ((size_t)(b * 16 + r) << 15);
        float4 s = make_float4(0.f, 0.f, 0.f, 0.f);
#pragma unroll
        for (int zz = -1; zz <= 1; ++zz) {
            int zin = z + zz;
            if ((unsigned)zin < 32u) {
                float4 v = *(const float4*)&base[(zin << 10) + p0];
                s.x += v.x; s.y += v.y; s.z += v.z; s.w += v.w;
            }
        }
        *(float4*)&zsum[(r << 10) + p0] = s;
    }
    __syncthreads();

    // y/x boxsum -> ls4[r] (float4 per rank)
    float4 ls4[16];
#pragma unroll
    for (int r = 0; r < 16; ++r) {
        float4 a = make_float4(0.f, 0.f, 0.f, 0.f);
#pragma unroll
        for (int dy = -1; dy <= 1; ++dy) {
            int yy = y + dy;
            if ((unsigned)yy < 32u) {
                const float* row = zsum + (r << 10) + (yy << 5);
                float4 c = *(const float4*)&row[x0];
                float lm = (x0 > 0)  ? row[x0 - 1] : 0.f;
                float rp = (x0 < 28) ? row[x0 + 4] : 0.f;
                a.x += lm  + c.x + c.y;
                a.y += c.x + c.y + c.z;
                a.z += c.y + c.z + c.w;
                a.w += c.z + c.w + rp;
            }
        }
        ls4[r] = a;
    }

    const size_t posb = ((size_t)(b * 128 + g * 32)) * 32768 + (z << 10) + p0;
#pragma unroll 4
    for (int oc = 0; oc < 32; ++oc) {
        float4 d = make_float4(0.f, 0.f, 0.f, 0.f);
        const float* w = &sB2[oc * 16];
#pragma unroll
        for (int r = 0; r < 16; ++r) {
            const float wv = w[r];
            d.x = fmaf(wv, ls4[r].x, d.x);
            d.y = fmaf(wv, ls4[r].y, d.y);
            d.z = fmaf(wv, ls4[r].z, d.z);
            d.w = fmaf(wv, ls4[r].w, d.w);
        }
        float4* op = (float4*)&out[posb + (size_t)oc * 32768];
        float4 o = *op;
        o.x += d.x; o.y += d.y; o.z += d.z; o.w += d.w;
        *op = o;
    }
}

// ---------------- launch ----------------
extern "C" void kernel_launch(void* const* d_in, const int* in_sizes, int n_in,
                              void* d_out, int out_size)
{
    const float* x      = (const float*)d_in[0];
    const float* weight = (const float*)d_in[1];
    const float* bias   = (const float*)d_in[2];
    const float* lora_A = (const float*)d_in[3];
    const float* lora_B = (const float*)d_in[4];
    float* out = (float*)d_out;

    cudaFuncSetAttribute(conv_mma_kernel,
                         cudaFuncAttributeMaxDynamicSharedMemorySize, SMEM_TOTAL);
    cudaFuncSetAttribute(lora_fused_kernel,
                         cudaFuncAttributeMaxDynamicSharedMemorySize, LORA_SMEM);

    pad_x_kernel<<<68, 256>>>(x);
    prep_w_kernel<<<144, 224>>>(weight, lora_A);
    conv_mma_kernel<<<512, 256, SMEM_TOTAL>>>(bias, out);
    lora_fused_kernel<<<256, 256, LORA_SMEM>>>(lora_B, out);
}

// round 9
// speedup vs baseline: 1.1395x; 1.1395x over previous
#include <cuda_runtime.h>
#include <cuda_fp16.h>
#include <cstdint>

// LoRAConv3d: out = conv3(x,[W;A]) -> (base+bias, low); out += 2*B@boxsum3(low)
// Implicit GEMM on mma.sync.m16n8k16 (f16 in, f32 acc).
// B=2, CIN=64, COUT=128, RANK=16, K=3^3, spatial 32^3, pad 1.

__device__ __half  xpad[2 * 34 * 34 * 34 * 64];   // padded NDHWC fp16
__device__ __half  wk[27 * 144 * 64];             // [off][n][c]
__device__ float   g_low[2 * 16 * 32768];

// ---------------- helpers ----------------
__device__ __forceinline__ uint32_t smem_u32(const void* p) {
    uint32_t a;
    asm("{ .reg .u64 t; cvta.to.shared.u64 t, %1; cvt.u32.u64 %0, t; }" : "=r"(a) : "l"(p));
    return a;
}
__device__ __forceinline__ void cp16(uint32_t dst, const void* src) {
    asm volatile("cp.async.cg.shared.global [%0], [%1], 16;" :: "r"(dst), "l"(src));
}
__device__ __forceinline__ void cp_commit() { asm volatile("cp.async.commit_group;"); }
template <int N> __device__ __forceinline__ void cp_wait() {
    asm volatile("cp.async.wait_group %0;" :: "n"(N) : "memory");
}
__device__ __forceinline__ void ldsm4(uint32_t* r, uint32_t addr) {
    asm volatile("ldmatrix.sync.aligned.m8n8.x4.shared.b16 {%0,%1,%2,%3}, [%4];"
                 : "=r"(r[0]), "=r"(r[1]), "=r"(r[2]), "=r"(r[3]) : "r"(addr));
}
__device__ __forceinline__ void ldsm2(uint32_t& b0, uint32_t& b1, uint32_t addr) {
    asm volatile("ldmatrix.sync.aligned.m8n8.x2.shared.b16 {%0,%1}, [%2];"
                 : "=r"(b0), "=r"(b1) : "r"(addr));
}
__device__ __forceinline__ void mma16816(float* c, const uint32_t* a,
                                         uint32_t b0, uint32_t b1) {
    asm volatile(
        "mma.sync.aligned.m16n8k16.row.col.f32.f16.f16.f32 "
        "{%0,%1,%2,%3}, {%4,%5,%6,%7}, {%8,%9}, {%0,%1,%2,%3};"
        : "+f"(c[0]), "+f"(c[1]), "+f"(c[2]), "+f"(c[3])
        : "r"(a[0]), "r"(a[1]), "r"(a[2]), "r"(a[3]), "r"(b0), "r"(b1));
}

// ---------------- prep kernels (R6 versions) ----------------
__global__ __launch_bounds__(256) void pad_x_kernel(const float* __restrict__ x) {
    int id = blockIdx.x;                       // 2*34*34
    int b = id / 1156, rem = id - b * 1156;
    int zp = rem / 34, yp = rem - zp * 34;
    const bool interior = (zp >= 1 && zp <= 32 && yp >= 1 && yp <= 32);
    __shared__ float s[2048];                  // [c][x]
    if (interior) {
        for (int i = threadIdx.x; i < 2048; i += 256) {
            int c = i >> 5, xx = i & 31;
            s[i] = x[((b * 64 + c) << 15) + ((zp - 1) << 10) + ((yp - 1) << 5) + xx];
        }
    }
    __syncthreads();
    __half* dst = xpad + (size_t)((b * 34 + zp) * 34 + yp) * 34 * 64;
    for (int i = threadIdx.x; i < 2176; i += 256) {
        int xi = i >> 6, c = i & 63;
        float v = (interior && xi >= 1 && xi <= 32) ? s[(c << 5) + (xi - 1)] : 0.f;
        dst[i] = __float2half(v);
    }
}

__global__ void prep_w_kernel(const float* __restrict__ weight,
                              const float* __restrict__ lora_A) {
    int i = blockIdx.x * 256 + threadIdx.x;    // 27*144*64
    if (i >= 27 * 144 * 64) return;
    int c = i & 63;
    int n = (i >> 6) % 144;
    int off = i / 9216;
    float v = (n < 128) ? weight[n * 1728 + c * 27 + off]
                        : lora_A[(n - 128) * 1728 + c * 27 + off];
    wk[i] = __float2half(v);
}

// ---------------- main conv: implicit GEMM on mma.sync ----------------
// per CTA: M=256 positions (4z x 8y x 8x), N=144, 27 offsets (K=64 each).
// halo: 6z x 10y x 10x = 600 rows x 144B. 512 threads, 1 CTA/SM.
#define SA_BYTES   (600 * 144)                 // 86400
#define SB_STRIDE  (144 * 144)                 // 20736
#define SB_OFF     SA_BYTES
#define SBIAS_OFF  (SA_BYTES + 2 * SB_STRIDE)  // 127872
#define SMEM_TOTAL (SBIAS_OFF + 512)           // 128384

__device__ __forceinline__ void stage_B(uint32_t buf, int off, int tid) {
    const char* wb = (const char*)wk + (size_t)off * 18432;
#pragma unroll
    for (int i = tid; i < 1152; i += 512) {
        int row = i >> 3, k = i & 7;
        cp16(buf + row * 144 + k * 16, wb + row * 128 + k * 16);
    }
}

__global__ __launch_bounds__(512, 1) void conv_mma_kernel(
    const float* __restrict__ bias, float* __restrict__ out)
{
    extern __shared__ char smem[];
    const uint32_t sb = smem_u32(smem);
    const uint32_t sA = sb, sB = sb + SB_OFF;
    float* sbias = (float*)(smem + SBIAS_OFF);

    const int tid = threadIdx.x, lane = tid & 31, wid = tid >> 5;
    const int t = blockIdx.x;                  // 256 tiles
    const int b  = t >> 7;
    const int r  = t & 127;                    // 8 z x 4 y x 4 x
    const int z0 = (r >> 4) * 4;
    const int y0 = ((r >> 2) & 3) * 8;
    const int x0 = (r & 3) * 8;

    if (tid < 128) sbias[tid] = bias[tid];

    // stage A halo: rows rr = (zz*10+yy)*10 + xx  (zz 0..5, yy 0..9, xx 0..9)
    {
        const char* xb = (const char*)xpad;
        for (int i = tid; i < 4800; i += 512) {
            int rr = i >> 3, k = i & 7;
            int zz = rr / 100, rem = rr - zz * 100;
            int yy = rem / 10, xx = rem - yy * 10;
            size_t src = ((size_t)(((b * 34 + z0 + zz) * 34 + (y0 + yy)) * 34 + (x0 + xx)))
                         * 128 + k * 16;
            cp16(sA + rr * 144 + k * 16, xb + src);
        }
    }
    stage_B(sB, 0, tid);
    cp_commit();

    const int m0w = (wid >> 1) * 32;           // 8 m-groups of 32
    const int n0w = (wid & 1) * 72;            // 2 n-groups of 72
    uint32_t laneA[2];
#pragma unroll
    for (int mi = 0; mi < 2; ++mi) {
        int m = m0w + mi * 16 + (lane & 15);
        int zi = m >> 6, yi = (m >> 3) & 7, xi = m & 7;
        laneA[mi] = (uint32_t)((zi * 100 + yi * 10 + xi) * 144 + ((lane >> 4) << 4));
    }
    const uint32_t laneB4 =
        (uint32_t)((n0w + ((lane >> 4) & 1) * 8 + (lane & 7)) * 144
                   + ((lane >> 3) & 1) * 16);
    const uint32_t laneB2 =
        (uint32_t)((n0w + 64 + (lane & 7)) * 144 + ((lane >> 3) & 1) * 16);

    float acc[2][9][4];
#pragma unroll
    for (int mi = 0; mi < 2; ++mi)
#pragma unroll
        for (int nj = 0; nj < 9; ++nj)
#pragma unroll
            for (int q = 0; q < 4; ++q) acc[mi][nj][q] = 0.f;

    for (int off = 0; off < 27; ++off) {
        cp_wait<0>();
        __syncthreads();
        if (off < 26) {
            stage_B(sB + ((off + 1) & 1) * SB_STRIDE, off + 1, tid);
            cp_commit();
        }
        const int dz = off / 9, r9 = off - dz * 9;
        const int dy = r9 / 3, dx = r9 - dy * 3;
        const uint32_t aoff = sA + (uint32_t)((dz * 100 + dy * 10 + dx) * 144);
        const uint32_t bb   = sB + (off & 1) * SB_STRIDE;
        const uint32_t b4   = bb + laneB4;
        const uint32_t b2   = bb + laneB2;

#pragma unroll
        for (int s = 0; s < 4; ++s) {
            const uint32_t so = (uint32_t)(s * 32);
            uint32_t a0[4], a1[4];
            ldsm4(a0, aoff + laneA[0] + so);
            ldsm4(a1, aoff + laneA[1] + so);
            uint32_t bf[18];
#pragma unroll
            for (int p = 0; p < 4; ++p) ldsm4(&bf[p * 4], b4 + p * 2304 + so);
            ldsm2(bf[16], bf[17], b2 + so);
#pragma unroll
            for (int nj = 0; nj < 9; ++nj) {
                const uint32_t bv0 = (nj < 8) ? bf[(nj >> 1) * 4 + (nj & 1) * 2] : bf[16];
                const uint32_t bv1 = (nj < 8) ? bf[(nj >> 1) * 4 + (nj & 1) * 2 + 1] : bf[17];
                mma16816(acc[0][nj], a0, bv0, bv1);
                mma16816(acc[1][nj], a1, bv0, bv1);
            }
        }
    }

    // epilogue
#pragma unroll
    for (int mi = 0; mi < 2; ++mi) {
        const int r0 = m0w + mi * 16 + (lane >> 2);
        const int r1 = r0 + 8;
        const int pos0 = (z0 + (r0 >> 6)) * 1024 + (y0 + ((r0 >> 3) & 7)) * 32
                         + x0 + (r0 & 7);
        const int pos1 = (z0 + (r1 >> 6)) * 1024 + (y0 + ((r1 >> 3) & 7)) * 32
                         + x0 + (r1 & 7);
#pragma unroll
        for (int nj = 0; nj < 9; ++nj) {
            const int c0 = n0w + nj * 8 + ((lane & 3) << 1);
#pragma unroll
            for (int q = 0; q < 4; ++q) {
                const int c = c0 + (q & 1);
                const int pos = (q < 2) ? pos0 : pos1;
                const float v = acc[mi][nj][q];
                if (c < 128)
                    out[(size_t)(b * 128 + c) * 32768 + pos] = v + sbias[c];
                else
                    g_low[(size_t)(b * 16 + (c - 128)) * 32768 + pos] = v;
            }
        }
    }
}

// ---------------- fused boxsum + lora apply (R6 version) ----------------
#define LORA_SMEM (16 * 1024 * 4 + 512 * 4)    // 67584
__global__ __launch_bounds__(1024) void lora_fused_kernel(
    const float* __restrict__ lora_B, float* __restrict__ out)
{
    extern __shared__ float lsm[];
    float* zsum = lsm;                 // [16][32*32]
    float* sB   = lsm + 16 * 1024;     // [32][16]

    const int id = blockIdx.x;         // 256 blocks: b*128 + z*4 + g
    const int g = id & 3, z = (id >> 2) & 31, b = id >> 7;
    const int tid = threadIdx.x;
    const int y = tid >> 5, xx = tid & 31;

    if (tid < 512) sB[tid] = lora_B[g * 512 + tid];

#pragma unroll
    for (int r = 0; r < 16; ++r) {
        const float* base = g_low + ((size_t)(b * 16 + r) << 15);
        float s = 0.f;
#pragma unroll
        for (int zz = -1; zz <= 1; ++zz) {
            int zin = z + zz;
            if ((unsigned)zin < 32u) s += base[(zin << 10) + tid];
        }
        zsum[(r << 10) + tid] = s;
    }
    __syncthreads();

    float ls[16];
#pragma unroll
    for (int r = 0; r < 16; ++r) {
        float a = 0.f;
#pragma unroll
        for (int dy = -1; dy <= 1; ++dy) {
            int yy = y + dy;
            if ((unsigned)yy < 32u) {
                const float* row = zsum + (r << 10) + (yy << 5);
#pragma unroll
                for (int dx = -1; dx <= 1; ++dx) {
                    int xn = xx + dx;
                    if ((unsigned)xn < 32u) a += row[xn];
                }
            }
        }
        ls[r] = a;
    }

    const size_t posb = ((size_t)(b * 128 + g * 32)) * 32768 + (z << 10) + tid;
#pragma unroll 4
    for (int oc = 0; oc < 32; ++oc) {
        float d = 0.f;
#pragma unroll
        for (int r = 0; r < 16; ++r) d = fmaf(sB[oc * 16 + r], ls[r], d);
        size_t idx = posb + (size_t)oc * 32768;
        out[idx] += 2.0f * d;
    }
}

// ---------------- launch ----------------
extern "C" void kernel_launch(void* const* d_in, const int* in_sizes, int n_in,
                              void* d_out, int out_size)
{
    const float* x      = (const float*)d_in[0];
    const float* weight = (const float*)d_in[1];
    const float* bias   = (const float*)d_in[2];
    const float* lora_A = (const float*)d_in[3];
    const float* lora_B = (const float*)d_in[4];
    float* out = (float*)d_out;

    cudaFuncSetAttribute(conv_mma_kernel,
                         cudaFuncAttributeMaxDynamicSharedMemorySize, SMEM_TOTAL);
    cudaFuncSetAttribute(lora_fused_kernel,
                         cudaFuncAttributeMaxDynamicSharedMemorySize, LORA_SMEM);

    pad_x_kernel<<<2312, 256>>>(x);
    prep_w_kernel<<<(27 * 144 * 64 + 255) / 256, 256>>>(weight, lora_A);
    conv_mma_kernel<<<256, 512, SMEM_TOTAL>>>(bias, out);
    lora_fused_kernel<<<256, 1024, LORA_SMEM>>>(lora_B, out);
}

// round 10
// speedup vs baseline: 1.1416x; 1.0019x over previous
#include <cuda_runtime.h>
#include <cuda_fp16.h>
#include <cstdint>

// LoRAConv3d: out = conv3(x,[W;A]) -> (base+bias, low); out += 2*B@boxsum3(low)
// Implicit GEMM on mma.sync.m16n8k16 (f16 in, f32 acc).
// B=2, CIN=64, COUT=128, RANK=16, K=3^3, spatial 32^3, pad 1.

__device__ __half  xpad[2 * 34 * 34 * 34 * 64];   // padded NDHWC fp16
__device__ __half  wk[27 * 144 * 64];             // [off][n][c]
__device__ float   g_low[2 * 16 * 32768];

// ---------------- helpers ----------------
__device__ __forceinline__ uint32_t smem_u32(const void* p) {
    uint32_t a;
    asm("{ .reg .u64 t; cvta.to.shared.u64 t, %1; cvt.u32.u64 %0, t; }" : "=r"(a) : "l"(p));
    return a;
}
__device__ __forceinline__ void cp16(uint32_t dst, const void* src) {
    asm volatile("cp.async.cg.shared.global [%0], [%1], 16;" :: "r"(dst), "l"(src));
}
__device__ __forceinline__ void cp_commit() { asm volatile("cp.async.commit_group;"); }
template <int N> __device__ __forceinline__ void cp_wait() {
    asm volatile("cp.async.wait_group %0;" :: "n"(N) : "memory");
}
__device__ __forceinline__ void ldsm4(uint32_t* r, uint32_t addr) {
    asm volatile("ldmatrix.sync.aligned.m8n8.x4.shared.b16 {%0,%1,%2,%3}, [%4];"
                 : "=r"(r[0]), "=r"(r[1]), "=r"(r[2]), "=r"(r[3]) : "r"(addr));
}
__device__ __forceinline__ void ldsm2(uint32_t& b0, uint32_t& b1, uint32_t addr) {
    asm volatile("ldmatrix.sync.aligned.m8n8.x2.shared.b16 {%0,%1}, [%2];"
                 : "=r"(b0), "=r"(b1) : "r"(addr));
}
__device__ __forceinline__ void mma16816(float* c, const uint32_t* a,
                                         uint32_t b0, uint32_t b1) {
    asm volatile(
        "mma.sync.aligned.m16n8k16.row.col.f32.f16.f16.f32 "
        "{%0,%1,%2,%3}, {%4,%5,%6,%7}, {%8,%9}, {%0,%1,%2,%3};"
        : "+f"(c[0]), "+f"(c[1]), "+f"(c[2]), "+f"(c[3])
        : "r"(a[0]), "r"(a[1]), "r"(a[2]), "r"(a[3]), "r"(b0), "r"(b1));
}

// ---------------- prep kernels ----------------
__global__ __launch_bounds__(256) void pad_x_kernel(const float* __restrict__ x) {
    int id = blockIdx.x;                       // 2*34*34
    int b = id / 1156, rem = id - b * 1156;
    int zp = rem / 34, yp = rem - zp * 34;
    const bool interior = (zp >= 1 && zp <= 32 && yp >= 1 && yp <= 32);
    __shared__ float s[2048];                  // [c][x]
    if (interior) {
        for (int i = threadIdx.x; i < 2048; i += 256) {
            int c = i >> 5, xx = i & 31;
            s[i] = x[((b * 64 + c) << 15) + ((zp - 1) << 10) + ((yp - 1) << 5) + xx];
        }
    }
    __syncthreads();
    __half* dst = xpad + (size_t)((b * 34 + zp) * 34 + yp) * 34 * 64;
    for (int i = threadIdx.x; i < 2176; i += 256) {
        int xi = i >> 6, c = i & 63;
        float v = (interior && xi >= 1 && xi <= 32) ? s[(c << 5) + (xi - 1)] : 0.f;
        dst[i] = __float2half(v);
    }
}

__global__ void prep_w_kernel(const float* __restrict__ weight,
                              const float* __restrict__ lora_A) {
    int i = blockIdx.x * 256 + threadIdx.x;    // 27*144*64
    if (i >= 27 * 144 * 64) return;
    int c = i & 63;
    int n = (i >> 6) % 144;
    int off = i / 9216;
    float v = (n < 128) ? weight[n * 1728 + c * 27 + off]
                        : lora_A[(n - 128) * 1728 + c * 27 + off];
    wk[i] = __float2half(v);
}

// ---------------- main conv: implicit GEMM on mma.sync ----------------
// per CTA: M=256 positions (4z x 8y x 8x), N=144, 27 offsets (K=64 each).
// halo: 6z x 10y x 10x = 600 rows x 144B. 512 threads, 1 CTA/SM.
// B weights: 3-stage cp.async ring, prefetch distance 2.
#define SA_BYTES   (600 * 144)                 // 86400
#define SB_STRIDE  (144 * 144)                 // 20736
#define SB_OFF     SA_BYTES
#define SBIAS_OFF  (SA_BYTES + 3 * SB_STRIDE)  // 148608
#define SMEM_TOTAL (SBIAS_OFF + 512)           // 149120

__device__ __forceinline__ void stage_B(uint32_t buf, int off, int tid) {
    const char* wb = (const char*)wk + (size_t)off * 18432;
#pragma unroll
    for (int i = tid; i < 1152; i += 512) {
        int row = i >> 3, k = i & 7;
        cp16(buf + row * 144 + k * 16, wb + row * 128 + k * 16);
    }
}

__global__ __launch_bounds__(512, 1) void conv_mma_kernel(
    const float* __restrict__ bias, float* __restrict__ out)
{
    extern __shared__ char smem[];
    const uint32_t sb = smem_u32(smem);
    const uint32_t sA = sb, sB = sb + SB_OFF;
    float* sbias = (float*)(smem + SBIAS_OFF);

    const int tid = threadIdx.x, lane = tid & 31, wid = tid >> 5;
    const int t = blockIdx.x;                  // 256 tiles
    const int b  = t >> 7;
    const int r  = t & 127;                    // 8 z x 4 y x 4 x
    const int z0 = (r >> 4) * 4;
    const int y0 = ((r >> 2) & 3) * 8;
    const int x0 = (r & 3) * 8;

    if (tid < 128) sbias[tid] = bias[tid];

    // stage A halo: rows rr = (zz*10+yy)*10 + xx  (zz 0..5, yy 0..9, xx 0..9)
    {
        const char* xb = (const char*)xpad;
        for (int i = tid; i < 4800; i += 512) {
            int rr = i >> 3, k = i & 7;
            int zz = rr / 100, rem = rr - zz * 100;
            int yy = rem / 10, xx = rem - yy * 10;
            size_t src = ((size_t)(((b * 34 + z0 + zz) * 34 + (y0 + yy)) * 34 + (x0 + xx)))
                         * 128 + k * 16;
            cp16(sA + rr * 144 + k * 16, xb + src);
        }
    }
    stage_B(sB, 0, tid);
    cp_commit();                               // G0: A + B0
    stage_B(sB + SB_STRIDE, 1, tid);
    cp_commit();                               // G1: B1

    const int m0w = (wid >> 1) * 32;           // 8 m-groups of 32
    const int n0w = (wid & 1) * 72;            // 2 n-groups of 72
    uint32_t laneA[2];
#pragma unroll
    for (int mi = 0; mi < 2; ++mi) {
        int m = m0w + mi * 16 + (lane & 15);
        int zi = m >> 6, yi = (m >> 3) & 7, xi = m & 7;
        laneA[mi] = (uint32_t)((zi * 100 + yi * 10 + xi) * 144 + ((lane >> 4) << 4));
    }
    const uint32_t laneB4 =
        (uint32_t)((n0w + ((lane >> 4) & 1) * 8 + (lane & 7)) * 144
                   + ((lane >> 3) & 1) * 16);
    const uint32_t laneB2 =
        (uint32_t)((n0w + 64 + (lane & 7)) * 144 + ((lane >> 3) & 1) * 16);

    float acc[2][9][4];
#pragma unroll
    for (int mi = 0; mi < 2; ++mi)
#pragma unroll
        for (int nj = 0; nj < 9; ++nj)
#pragma unroll
            for (int q = 0; q < 4; ++q) acc[mi][nj][q] = 0.f;

    int buf = 0;                               // off % 3
    for (int off = 0; off < 27; ++off) {
        if (off < 26) cp_wait<1>();            // G_off done (groups retire in order)
        else          cp_wait<0>();
        __syncthreads();
        if (off + 2 < 27) {
            int nb = buf + 2; if (nb >= 3) nb -= 3;
            stage_B(sB + nb * SB_STRIDE, off + 2, tid);
            cp_commit();
        }
        const int dz = off / 9, r9 = off - dz * 9;
        const int dy = r9 / 3, dx = r9 - dy * 3;
        const uint32_t aoff = sA + (uint32_t)((dz * 100 + dy * 10 + dx) * 144);
        const uint32_t bb   = sB + buf * SB_STRIDE;
        const uint32_t b4   = bb + laneB4;
        const uint32_t b2   = bb + laneB2;

#pragma unroll
        for (int s = 0; s < 4; ++s) {
            const uint32_t so = (uint32_t)(s * 32);
            uint32_t a0[4], a1[4];
            ldsm4(a0, aoff + laneA[0] + so);
            ldsm4(a1, aoff + laneA[1] + so);
            uint32_t bf[18];
#pragma unroll
            for (int p = 0; p < 4; ++p) ldsm4(&bf[p * 4], b4 + p * 2304 + so);
            ldsm2(bf[16], bf[17], b2 + so);
#pragma unroll
            for (int nj = 0; nj < 9; ++nj) {
                const uint32_t bv0 = (nj < 8) ? bf[(nj >> 1) * 4 + (nj & 1) * 2] : bf[16];
                const uint32_t bv1 = (nj < 8) ? bf[(nj >> 1) * 4 + (nj & 1) * 2 + 1] : bf[17];
                mma16816(acc[0][nj], a0, bv0, bv1);
                mma16816(acc[1][nj], a1, bv0, bv1);
            }
        }
        if (++buf >= 3) buf = 0;
    }

    // epilogue
#pragma unroll
    for (int mi = 0; mi < 2; ++mi) {
        const int r0 = m0w + mi * 16 + (lane >> 2);
        const int r1 = r0 + 8;
        const int pos0 = (z0 + (r0 >> 6)) * 1024 + (y0 + ((r0 >> 3) & 7)) * 32
                         + x0 + (r0 & 7);
        const int pos1 = (z0 + (r1 >> 6)) * 1024 + (y0 + ((r1 >> 3) & 7)) * 32
                         + x0 + (r1 & 7);
#pragma unroll
        for (int nj = 0; nj < 9; ++nj) {
            const int c0 = n0w + nj * 8 + ((lane & 3) << 1);
#pragma unroll
            for (int q = 0; q < 4; ++q) {
                const int c = c0 + (q & 1);
                const int pos = (q < 2) ? pos0 : pos1;
                const float v = acc[mi][nj][q];
                if (c < 128)
                    out[(size_t)(b * 128 + c) * 32768 + pos] = v + sbias[c];
                else
                    g_low[(size_t)(b * 16 + (c - 128)) * 32768 + pos] = v;
            }
        }
    }
}

// ---------------- fused boxsum + lora apply ----------------
#define LORA_SMEM (16 * 1024 * 4 + 512 * 4)    // 67584
__global__ __launch_bounds__(1024) void lora_fused_kernel(
    const float* __restrict__ lora_B, float* __restrict__ out)
{
    extern __shared__ float lsm[];
    float* zsum = lsm;                 // [16][32*32]
    float* sB   = lsm + 16 * 1024;     // [32][16]

    const int id = blockIdx.x;         // 256 blocks: b*128 + z*4 + g
    const int g = id & 3, z = (id >> 2) & 31, b = id >> 7;
    const int tid = threadIdx.x;
    const int y = tid >> 5, xx = tid & 31;

    if (tid < 512) sB[tid] = lora_B[g * 512 + tid];

#pragma unroll
    for (int r = 0; r < 16; ++r) {
        const float* base = g_low + ((size_t)(b * 16 + r) << 15);
        float s = 0.f;
#pragma unroll
        for (int zz = -1; zz <= 1; ++zz) {
            int zin = z + zz;
            if ((unsigned)zin < 32u) s += base[(zin << 10) + tid];
        }
        zsum[(r << 10) + tid] = s;
    }
    __syncthreads();

    float ls[16];
#pragma unroll
    for (int r = 0; r < 16; ++r) {
        float a = 0.f;
#pragma unroll
        for (int dy = -1; dy <= 1; ++dy) {
            int yy = y + dy;
            if ((unsigned)yy < 32u) {
                const float* row = zsum + (r << 10) + (yy << 5);
#pragma unroll
                for (int dx = -1; dx <= 1; ++dx) {
                    int xn = xx + dx;
                    if ((unsigned)xn < 32u) a += row[xn];
                }
            }
        }
        ls[r] = a;
    }

    const size_t posb = ((size_t)(b * 128 + g * 32)) * 32768 + (z << 10) + tid;
#pragma unroll 4
    for (int oc = 0; oc < 32; ++oc) {
        float d = 0.f;
#pragma unroll
        for (int r = 0; r < 16; ++r) d = fmaf(sB[oc * 16 + r], ls[r], d);
        size_t idx = posb + (size_t)oc * 32768;
        out[idx] += 2.0f * d;
    }
}

// ---------------- launch ----------------
extern "C" void kernel_launch(void* const* d_in, const int* in_sizes, int n_in,
                              void* d_out, int out_size)
{
    const float* x      = (const float*)d_in[0];
    const float* weight = (const float*)d_in[1];
    const float* bias   = (const float*)d_in[2];
    const float* lora_A = (const float*)d_in[3];
    const float* lora_B = (const float*)d_in[4];
    float* out = (float*)d_out;

    cudaFuncSetAttribute(conv_mma_kernel,
                         cudaFuncAttributeMaxDynamicSharedMemorySize, SMEM_TOTAL);
    cudaFuncSetAttribute(lora_fused_kernel,
                         cudaFuncAttributeMaxDynamicSharedMemorySize, LORA_SMEM);

    pad_x_kernel<<<2312, 256>>>(x);
    prep_w_kernel<<<(27 * 144 * 64 + 255) / 256, 256>>>(weight, lora_A);
    conv_mma_kernel<<<256, 512, SMEM_TOTAL>>>(bias, out);
    lora_fused_kernel<<<256, 1024, LORA_SMEM>>>(lora_B, out);
}

// round 11
// speedup vs baseline: 1.1616x; 1.0175x over previous
#include <cuda_runtime.h>
#include <cuda_fp16.h>
#include <cstdint>

// LoRAConv3d: out = conv3(x,[W;A]) -> (base+bias, low); out += 2*B@boxsum3(low)
// Implicit GEMM on mma.sync.m16n8k16 (f16 in, f32 acc).
// B=2, CIN=64, COUT=128, RANK=16, K=3^3, spatial 32^3, pad 1.

__device__ __half  xpad[2 * 34 * 34 * 34 * 64];   // padded NDHWC fp16
__device__ __half  wk[27 * 144 * 64];             // [off][n][c]
__device__ float   g_low[2 * 16 * 32768];

// ---------------- helpers ----------------
__device__ __forceinline__ uint32_t smem_u32(const void* p) {
    uint32_t a;
    asm("{ .reg .u64 t; cvta.to.shared.u64 t, %1; cvt.u32.u64 %0, t; }" : "=r"(a) : "l"(p));
    return a;
}
__device__ __forceinline__ void cp16(uint32_t dst, const void* src) {
    asm volatile("cp.async.cg.shared.global [%0], [%1], 16;" :: "r"(dst), "l"(src));
}
__device__ __forceinline__ void cp_commit() { asm volatile("cp.async.commit_group;"); }
template <int N> __device__ __forceinline__ void cp_wait() {
    asm volatile("cp.async.wait_group %0;" :: "n"(N) : "memory");
}
__device__ __forceinline__ void ldsm4(uint32_t* r, uint32_t addr) {
    asm volatile("ldmatrix.sync.aligned.m8n8.x4.shared.b16 {%0,%1,%2,%3}, [%4];"
                 : "=r"(r[0]), "=r"(r[1]), "=r"(r[2]), "=r"(r[3]) : "r"(addr));
}
__device__ __forceinline__ void mma16816(float* c, const uint32_t* a,
                                         uint32_t b0, uint32_t b1) {
    asm volatile(
        "mma.sync.aligned.m16n8k16.row.col.f32.f16.f16.f32 "
        "{%0,%1,%2,%3}, {%4,%5,%6,%7}, {%8,%9}, {%0,%1,%2,%3};"
        : "+f"(c[0]), "+f"(c[1]), "+f"(c[2]), "+f"(c[3])
        : "r"(a[0]), "r"(a[1]), "r"(a[2]), "r"(a[3]), "r"(b0), "r"(b1));
}

// ---------------- prep kernels ----------------
__global__ __launch_bounds__(256) void pad_x_kernel(const float* __restrict__ x) {
    int id = blockIdx.x;                       // 2*34*34
    int b = id / 1156, rem = id - b * 1156;
    int zp = rem / 34, yp = rem - zp * 34;
    const bool interior = (zp >= 1 && zp <= 32 && yp >= 1 && yp <= 32);
    __shared__ float s[2048];                  // [c][x]
    if (interior) {
        for (int i = threadIdx.x; i < 2048; i += 256) {
            int c = i >> 5, xx = i & 31;
            s[i] = x[((b * 64 + c) << 15) + ((zp - 1) << 10) + ((yp - 1) << 5) + xx];
        }
    }
    __syncthreads();
    __half* dst = xpad + (size_t)((b * 34 + zp) * 34 + yp) * 34 * 64;
    for (int i = threadIdx.x; i < 2176; i += 256) {
        int xi = i >> 6, c = i & 63;
        float v = (interior && xi >= 1 && xi <= 32) ? s[(c << 5) + (xi - 1)] : 0.f;
        dst[i] = __float2half(v);
    }
}

__global__ void prep_w_kernel(const float* __restrict__ weight,
                              const float* __restrict__ lora_A) {
    int i = blockIdx.x * 256 + threadIdx.x;    // 27*144*64
    if (i >= 27 * 144 * 64) return;
    int c = i & 63;
    int n = (i >> 6) % 144;
    int off = i / 9216;
    float v = (n < 128) ? weight[n * 1728 + c * 27 + off]
                        : lora_A[(n - 128) * 1728 + c * 27 + off];
    wk[i] = __float2half(v);
}

// ---------------- main conv: implicit GEMM on mma.sync ----------------
// per CTA: M=256 positions (4z x 8y x 8x), N=144, 27 offsets (K=64 each).
// 768 threads = 24 warps: 8 m-groups(32) x 3 n-groups(48). 1 CTA/SM.
#define SA_BYTES   (600 * 144)                 // 86400
#define SB_STRIDE  (144 * 144)                 // 20736
#define SB_OFF     SA_BYTES
#define SBIAS_OFF  (SA_BYTES + 2 * SB_STRIDE)  // 127872
#define SMEM_TOTAL (SBIAS_OFF + 512)           // 128384

__device__ __forceinline__ void stage_B(uint32_t buf, int off, int tid) {
    const char* wb = (const char*)wk + (size_t)off * 18432;
#pragma unroll
    for (int i = tid; i < 1152; i += 768) {
        int row = i >> 3, k = i & 7;
        cp16(buf + row * 144 + k * 16, wb + row * 128 + k * 16);
    }
}

__global__ __launch_bounds__(768, 1) void conv_mma_kernel(
    const float* __restrict__ bias, float* __restrict__ out)
{
    extern __shared__ char smem[];
    const uint32_t sb = smem_u32(smem);
    const uint32_t sA = sb, sB = sb + SB_OFF;
    float* sbias = (float*)(smem + SBIAS_OFF);

    const int tid = threadIdx.x, lane = tid & 31, wid = tid >> 5;
    const int t = blockIdx.x;                  // 256 tiles
    const int b  = t >> 7;
    const int r  = t & 127;                    // 8 z x 4 y x 4 x
    const int z0 = (r >> 4) * 4;
    const int y0 = ((r >> 2) & 3) * 8;
    const int x0 = (r & 3) * 8;

    if (tid < 128) sbias[tid] = bias[tid];

    // stage A halo: rows rr = (zz*10+yy)*10 + xx  (zz 0..5, yy 0..9, xx 0..9)
    {
        const char* xb = (const char*)xpad;
        for (int i = tid; i < 4800; i += 768) {
            int rr = i >> 3, k = i & 7;
            int zz = rr / 100, rem = rr - zz * 100;
            int yy = rem / 10, xx = rem - yy * 10;
            size_t src = ((size_t)(((b * 34 + z0 + zz) * 34 + (y0 + yy)) * 34 + (x0 + xx)))
                         * 128 + k * 16;
            cp16(sA + rr * 144 + k * 16, xb + src);
        }
    }
    stage_B(sB, 0, tid);
    cp_commit();

    const int m0w = (wid & 7) * 32;            // 8 m-groups of 32
    const int n0w = (wid >> 3) * 48;           // 3 n-groups of 48
    uint32_t laneA[2];
#pragma unroll
    for (int mi = 0; mi < 2; ++mi) {
        int m = m0w + mi * 16 + (lane & 15);
        int zi = m >> 6, yi = (m >> 3) & 7, xi = m & 7;
        laneA[mi] = (uint32_t)((zi * 100 + yi * 10 + xi) * 144 + ((lane >> 4) << 4));
    }
    // paired-n ldsm4: lanes 0-7 rows p*16+0..7 koff0; 8-15 koff16; 16-23 rows +8..15 koff0; 24-31 koff16
    const uint32_t laneB4 =
        (uint32_t)((n0w + ((lane >> 4) & 1) * 8 + (lane & 7)) * 144
                   + ((lane >> 3) & 1) * 16);

    float acc[2][6][4];
#pragma unroll
    for (int mi = 0; mi < 2; ++mi)
#pragma unroll
        for (int nj = 0; nj < 6; ++nj)
#pragma unroll
            for (int q = 0; q < 4; ++q) acc[mi][nj][q] = 0.f;

    for (int off = 0; off < 27; ++off) {
        cp_wait<0>();
        __syncthreads();
        if (off < 26) {
            stage_B(sB + ((off + 1) & 1) * SB_STRIDE, off + 1, tid);
            cp_commit();
        }
        const int dz = off / 9, r9 = off - dz * 9;
        const int dy = r9 / 3, dx = r9 - dy * 3;
        const uint32_t aoff = sA + (uint32_t)((dz * 100 + dy * 10 + dx) * 144);
        const uint32_t b4   = sB + (off & 1) * SB_STRIDE + laneB4;

#pragma unroll
        for (int s = 0; s < 4; ++s) {
            const uint32_t so = (uint32_t)(s * 32);
            uint32_t a0[4], a1[4];
            ldsm4(a0, aoff + laneA[0] + so);
            ldsm4(a1, aoff + laneA[1] + so);
            uint32_t bf[12];
#pragma unroll
            for (int p = 0; p < 3; ++p) ldsm4(&bf[p * 4], b4 + p * 2304 + so);
#pragma unroll
            for (int nj = 0; nj < 6; ++nj) {
                const uint32_t bv0 = bf[(nj >> 1) * 4 + (nj & 1) * 2];
                const uint32_t bv1 = bf[(nj >> 1) * 4 + (nj & 1) * 2 + 1];
                mma16816(acc[0][nj], a0, bv0, bv1);
                mma16816(acc[1][nj], a1, bv0, bv1);
            }
        }
    }

    // epilogue
#pragma unroll
    for (int mi = 0; mi < 2; ++mi) {
        const int r0 = m0w + mi * 16 + (lane >> 2);
        const int r1 = r0 + 8;
        const int pos0 = (z0 + (r0 >> 6)) * 1024 + (y0 + ((r0 >> 3) & 7)) * 32
                         + x0 + (r0 & 7);
        const int pos1 = (z0 + (r1 >> 6)) * 1024 + (y0 + ((r1 >> 3) & 7)) * 32
                         + x0 + (r1 & 7);
#pragma unroll
        for (int nj = 0; nj < 6; ++nj) {
            const int c0 = n0w + nj * 8 + ((lane & 3) << 1);
#pragma unroll
            for (int q = 0; q < 4; ++q) {
                const int c = c0 + (q & 1);
                const int pos = (q < 2) ? pos0 : pos1;
                const float v = acc[mi][nj][q];
                if (c < 128)
                    out[(size_t)(b * 128 + c) * 32768 + pos] = v + sbias[c];
                else
                    g_low[(size_t)(b * 16 + (c - 128)) * 32768 + pos] = v;
            }
        }
    }
}

// ---------------- fused boxsum + lora apply ----------------
#define LORA_SMEM (16 * 1024 * 4 + 512 * 4)    // 67584
__global__ __launch_bounds__(1024) void lora_fused_kernel(
    const float* __restrict__ lora_B, float* __restrict__ out)
{
    extern __shared__ float lsm[];
    float* zsum = lsm;                 // [16][32*32]
    float* sB   = lsm + 16 * 1024;     // [32][16]

    const int id = blockIdx.x;         // 256 blocks: b*128 + z*4 + g
    const int g = id & 3, z = (id >> 2) & 31, b = id >> 7;
    const int tid = threadIdx.x;
    const int y = tid >> 5, xx = tid & 31;

    if (tid < 512) sB[tid] = lora_B[g * 512 + tid];

#pragma unroll
    for (int r = 0; r < 16; ++r) {
        const float* base = g_low + ((size_t)(b * 16 + r) << 15);
        float s = 0.f;
#pragma unroll
        for (int zz = -1; zz <= 1; ++zz) {
            int zin = z + zz;
            if ((unsigned)zin < 32u) s += base[(zin << 10) + tid];
        }
        zsum[(r << 10) + tid] = s;
    }
    __syncthreads();

    float ls[16];
#pragma unroll
    for (int r = 0; r < 16; ++r) {
        float a = 0.f;
#pragma unroll
        for (int dy = -1; dy <= 1; ++dy) {
            int yy = y + dy;
            if ((unsigned)yy < 32u) {
                const float* row = zsum + (r << 10) + (yy << 5);
#pragma unroll
                for (int dx = -1; dx <= 1; ++dx) {
                    int xn = xx + dx;
                    if ((unsigned)xn < 32u) a += row[xn];
                }
            }
        }
        ls[r] = a;
    }

    const size_t posb = ((size_t)(b * 128 + g * 32)) * 32768 + (z << 10) + tid;
#pragma unroll 4
    for (int oc = 0; oc < 32; ++oc) {
        float d = 0.f;
#pragma unroll
        for (int r = 0; r < 16; ++r) d = fmaf(sB[oc * 16 + r], ls[r], d);
        size_t idx = posb + (size_t)oc * 32768;
        out[idx] += 2.0f * d;
    }
}

// ---------------- launch ----------------
extern "C" void kernel_launch(void* const* d_in, const int* in_sizes, int n_in,
                              void* d_out, int out_size)
{
    const float* x      = (const float*)d_in[0];
    const float* weight = (const float*)d_in[1];
    const float* bias   = (const float*)d_in[2];
    const float* lora_A = (const float*)d_in[3];
    const float* lora_B = (const float*)d_in[4];
    float* out = (float*)d_out;

    cudaFuncSetAttribute(conv_mma_kernel,
                         cudaFuncAttributeMaxDynamicSharedMemorySize, SMEM_TOTAL);
    cudaFuncSetAttribute(lora_fused_kernel,
                         cudaFuncAttributeMaxDynamicSharedMemorySize, LORA_SMEM);

    pad_x_kernel<<<2312, 256>>>(x);
    prep_w_kernel<<<(27 * 144 * 64 + 255) / 256, 256>>>(weight, lora_A);
    conv_mma_kernel<<<256, 768, SMEM_TOTAL>>>(bias, out);
    lora_fused_kernel<<<256, 1024, LORA_SMEM>>>(lora_B, out);
}

// round 12
// speedup vs baseline: 1.3146x; 1.1317x over previous
#include <cuda_runtime.h>
#include <cuda_fp16.h>
#include <cstdint>

// LoRAConv3d: out = conv3(x,[W;A]) -> (base+bias, low); out += 2*B@boxsum3(low)
// Implicit GEMM on mma.sync.m16n8k16 (f16 in, f32 acc).
// B=2, CIN=64, COUT=128, RANK=16, K=3^3, spatial 32^3, pad 1.

__device__ __half  xpad[2 * 34 * 34 * 34 * 64];   // padded NDHWC fp16
__device__ __half  wk[27 * 144 * 64];             // [off][n][c]
__device__ float   g_low[2 * 16 * 32768];

// ---------------- helpers ----------------
__device__ __forceinline__ uint32_t smem_u32(const void* p) {
    uint32_t a;
    asm("{ .reg .u64 t; cvta.to.shared.u64 t, %1; cvt.u32.u64 %0, t; }" : "=r"(a) : "l"(p));
    return a;
}
__device__ __forceinline__ void cp16(uint32_t dst, const void* src) {
    asm volatile("cp.async.cg.shared.global [%0], [%1], 16;" :: "r"(dst), "l"(src));
}
__device__ __forceinline__ void cp_commit() { asm volatile("cp.async.commit_group;"); }
template <int N> __device__ __forceinline__ void cp_wait() {
    asm volatile("cp.async.wait_group %0;" :: "n"(N) : "memory");
}
__device__ __forceinline__ void ldsm4(uint32_t* r, uint32_t addr) {
    asm volatile("ldmatrix.sync.aligned.m8n8.x4.shared.b16 {%0,%1,%2,%3}, [%4];"
                 : "=r"(r[0]), "=r"(r[1]), "=r"(r[2]), "=r"(r[3]) : "r"(addr));
}
__device__ __forceinline__ void mma16816(float* c, const uint32_t* a,
                                         uint32_t b0, uint32_t b1) {
    asm volatile(
        "mma.sync.aligned.m16n8k16.row.col.f32.f16.f16.f32 "
        "{%0,%1,%2,%3}, {%4,%5,%6,%7}, {%8,%9}, {%0,%1,%2,%3};"
        : "+f"(c[0]), "+f"(c[1]), "+f"(c[2]), "+f"(c[3])
        : "r"(a[0]), "r"(a[1]), "r"(a[2]), "r"(a[3]), "r"(b0), "r"(b1));
}

// ---------------- merged prep kernel ----------------
// blocks 0..2311: pad/transpose x -> xpad (one (b,zp,yp) row-plane each)
// blocks 2312..2455: weight transpose -> wk (one output channel each)
__global__ __launch_bounds__(256) void prep_kernel(
    const float* __restrict__ x,
    const float* __restrict__ weight,
    const float* __restrict__ lora_A)
{
    __shared__ float s[2304];                  // pad: [32][72]; prep_w: [1728]
    const int id = blockIdx.x;
    if (id < 2312) {
        int b = id / 1156, rem = id - b * 1156;
        int zp = rem / 34, yp = rem - zp * 34;
        const bool interior = (zp >= 1 && zp <= 32 && yp >= 1 && yp <= 32);
        if (interior) {
            for (int i = threadIdx.x; i < 2048; i += 256) {
                int c = i >> 5, xx = i & 31;
                s[xx * 72 + c] =
                    x[((b * 64 + c) << 15) + ((zp - 1) << 10) + ((yp - 1) << 5) + xx];
            }
        }
        __syncthreads();
        uint4* dst = (uint4*)(xpad + (size_t)((b * 34 + zp) * 34 + yp) * 34 * 64);
        for (int i = threadIdx.x; i < 272; i += 256) {   // 34x64 halves = 272 uint4
            int xi = i >> 3, c0 = (i & 7) << 3;
            uint4 o = make_uint4(0u, 0u, 0u, 0u);
            if (interior && xi >= 1 && xi <= 32) {
                const float* sp = &s[(xi - 1) * 72 + c0];
                __half2 h0 = __floats2half2_rn(sp[0], sp[1]);
                __half2 h1 = __floats2half2_rn(sp[2], sp[3]);
                __half2 h2 = __floats2half2_rn(sp[4], sp[5]);
                __half2 h3 = __floats2half2_rn(sp[6], sp[7]);
                o.x = *(uint32_t*)&h0; o.y = *(uint32_t*)&h1;
                o.z = *(uint32_t*)&h2; o.w = *(uint32_t*)&h3;
            }
            dst[i] = o;
        }
    } else {
        const int n = id - 2312;               // 0..143
        const float* src = (n < 128) ? (weight + (size_t)n * 1728)
                                     : (lora_A + (size_t)(n - 128) * 1728);
        for (int i = threadIdx.x; i < 432; i += 256)
            *(float4*)&s[i * 4] = *(const float4*)&src[i * 4];
        __syncthreads();
        for (int i = threadIdx.x; i < 432; i += 256) {
            int off = i >> 4, c0 = (i & 15) << 2;
            __half2 h0 = __floats2half2_rn(s[c0 * 27 + off], s[(c0 + 1) * 27 + off]);
            __half2 h1 = __floats2half2_rn(s[(c0 + 2) * 27 + off], s[(c0 + 3) * 27 + off]);
            uint2 o; o.x = *(uint32_t*)&h0; o.y = *(uint32_t*)&h1;
            *(uint2*)&wk[(size_t)off * 9216 + n * 64 + c0] = o;
        }
    }
}

// ---------------- main conv: implicit GEMM on mma.sync (R11, unchanged) ----------------
// per CTA: M=256 positions (4z x 8y x 8x), N=144, 27 offsets (K=64 each).
// 768 threads = 24 warps: 8 m-groups(32) x 3 n-groups(48). 1 CTA/SM.
#define SA_BYTES   (600 * 144)                 // 86400
#define SB_STRIDE  (144 * 144)                 // 20736
#define SB_OFF     SA_BYTES
#define SBIAS_OFF  (SA_BYTES + 2 * SB_STRIDE)  // 127872
#define SMEM_TOTAL (SBIAS_OFF + 512)           // 128384

__device__ __forceinline__ void stage_B(uint32_t buf, int off, int tid) {
    const char* wb = (const char*)wk + (size_t)off * 18432;
#pragma unroll
    for (int i = tid; i < 1152; i += 768) {
        int row = i >> 3, k = i & 7;
        cp16(buf + row * 144 + k * 16, wb + row * 128 + k * 16);
    }
}

__global__ __launch_bounds__(768, 1) void conv_mma_kernel(
    const float* __restrict__ bias, float* __restrict__ out)
{
    extern __shared__ char smem[];
    const uint32_t sb = smem_u32(smem);
    const uint32_t sA = sb, sB = sb + SB_OFF;
    float* sbias = (float*)(smem + SBIAS_OFF);

    const int tid = threadIdx.x, lane = tid & 31, wid = tid >> 5;
    const int t = blockIdx.x;                  // 256 tiles
    const int b  = t >> 7;
    const int r  = t & 127;                    // 8 z x 4 y x 4 x
    const int z0 = (r >> 4) * 4;
    const int y0 = ((r >> 2) & 3) * 8;
    const int x0 = (r & 3) * 8;

    if (tid < 128) sbias[tid] = bias[tid];

    // stage A halo: rows rr = (zz*10+yy)*10 + xx  (zz 0..5, yy 0..9, xx 0..9)
    {
        const char* xb = (const char*)xpad;
        for (int i = tid; i < 4800; i += 768) {
            int rr = i >> 3, k = i & 7;
            int zz = rr / 100, rem = rr - zz * 100;
            int yy = rem / 10, xx = rem - yy * 10;
            size_t src = ((size_t)(((b * 34 + z0 + zz) * 34 + (y0 + yy)) * 34 + (x0 + xx)))
                         * 128 + k * 16;
            cp16(sA + rr * 144 + k * 16, xb + src);
        }
    }
    stage_B(sB, 0, tid);
    cp_commit();

    const int m0w = (wid & 7) * 32;            // 8 m-groups of 32
    const int n0w = (wid >> 3) * 48;           // 3 n-groups of 48
    uint32_t laneA[2];
#pragma unroll
    for (int mi = 0; mi < 2; ++mi) {
        int m = m0w + mi * 16 + (lane & 15);
        int zi = m >> 6, yi = (m >> 3) & 7, xi = m & 7;
        laneA[mi] = (uint32_t)((zi * 100 + yi * 10 + xi) * 144 + ((lane >> 4) << 4));
    }
    const uint32_t laneB4 =
        (uint32_t)((n0w + ((lane >> 4) & 1) * 8 + (lane & 7)) * 144
                   + ((lane >> 3) & 1) * 16);

    float acc[2][6][4];
#pragma unroll
    for (int mi = 0; mi < 2; ++mi)
#pragma unroll
        for (int nj = 0; nj < 6; ++nj)
#pragma unroll
            for (int q = 0; q < 4; ++q) acc[mi][nj][q] = 0.f;

    for (int off = 0; off < 27; ++off) {
        cp_wait<0>();
        __syncthreads();
        if (off < 26) {
            stage_B(sB + ((off + 1) & 1) * SB_STRIDE, off + 1, tid);
            cp_commit();
        }
        const int dz = off / 9, r9 = off - dz * 9;
        const int dy = r9 / 3, dx = r9 - dy * 3;
        const uint32_t aoff = sA + (uint32_t)((dz * 100 + dy * 10 + dx) * 144);
        const uint32_t b4   = sB + (off & 1) * SB_STRIDE + laneB4;

#pragma unroll
        for (int s = 0; s < 4; ++s) {
            const uint32_t so = (uint32_t)(s * 32);
            uint32_t a0[4], a1[4];
            ldsm4(a0, aoff + laneA[0] + so);
            ldsm4(a1, aoff + laneA[1] + so);
            uint32_t bf[12];
#pragma unroll
            for (int p = 0; p < 3; ++p) ldsm4(&bf[p * 4], b4 + p * 2304 + so);
#pragma unroll
            for (int nj = 0; nj < 6; ++nj) {
                const uint32_t bv0 = bf[(nj >> 1) * 4 + (nj & 1) * 2];
                const uint32_t bv1 = bf[(nj >> 1) * 4 + (nj & 1) * 2 + 1];
                mma16816(acc[0][nj], a0, bv0, bv1);
                mma16816(acc[1][nj], a1, bv0, bv1);
            }
        }
    }

    // epilogue
#pragma unroll
    for (int mi = 0; mi < 2; ++mi) {
        const int r0 = m0w + mi * 16 + (lane >> 2);
        const int r1 = r0 + 8;
        const int pos0 = (z0 + (r0 >> 6)) * 1024 + (y0 + ((r0 >> 3) & 7)) * 32
                         + x0 + (r0 & 7);
        const int pos1 = (z0 + (r1 >> 6)) * 1024 + (y0 + ((r1 >> 3) & 7)) * 32
                         + x0 + (r1 & 7);
#pragma unroll
        for (int nj = 0; nj < 6; ++nj) {
            const int c0 = n0w + nj * 8 + ((lane & 3) << 1);
#pragma unroll
            for (int q = 0; q < 4; ++q) {
                const int c = c0 + (q & 1);
                const int pos = (q < 2) ? pos0 : pos1;
                const float v = acc[mi][nj][q];
                if (c < 128)
                    out[(size_t)(b * 128 + c) * 32768 + pos] = v + sbias[c];
                else
                    g_low[(size_t)(b * 16 + (c - 128)) * 32768 + pos] = v;
            }
        }
    }
}

// ---------------- fused boxsum + lora apply (unchanged) ----------------
#define LORA_SMEM (16 * 1024 * 4 + 512 * 4)    // 67584
__global__ __launch_bounds__(1024) void lora_fused_kernel(
    const float* __restrict__ lora_B, float* __restrict__ out)
{
    extern __shared__ float lsm[];
    float* zsum = lsm;                 // [16][32*32]
    float* sB   = lsm + 16 * 1024;     // [32][16]

    const int id = blockIdx.x;         // 256 blocks: b*128 + z*4 + g
    const int g = id & 3, z = (id >> 2) & 31, b = id >> 7;
    const int tid = threadIdx.x;
    const int y = tid >> 5, xx = tid & 31;

    if (tid < 512) sB[tid] = lora_B[g * 512 + tid];

#pragma unroll
    for (int r = 0; r < 16; ++r) {
        const float* base = g_low + ((size_t)(b * 16 + r) << 15);
        float s = 0.f;
#pragma unroll
        for (int zz = -1; zz <= 1; ++zz) {
            int zin = z + zz;
            if ((unsigned)zin < 32u) s += base[(zin << 10) + tid];
        }
        zsum[(r << 10) + tid] = s;
    }
    __syncthreads();

    float ls[16];
#pragma unroll
    for (int r = 0; r < 16; ++r) {
        float a = 0.f;
#pragma unroll
        for (int dy = -1; dy <= 1; ++dy) {
            int yy = y + dy;
            if ((unsigned)yy < 32u) {
                const float* row = zsum + (r << 10) + (yy << 5);
#pragma unroll
                for (int dx = -1; dx <= 1; ++dx) {
                    int xn = xx + dx;
                    if ((unsigned)xn < 32u) a += row[xn];
                }
            }
        }
        ls[r] = a;
    }

    const size_t posb = ((size_t)(b * 128 + g * 32)) * 32768 + (z << 10) + tid;
#pragma unroll 4
    for (int oc = 0; oc < 32; ++oc) {
        float d = 0.f;
#pragma unroll
        for (int r = 0; r < 16; ++r) d = fmaf(sB[oc * 16 + r], ls[r], d);
        size_t idx = posb + (size_t)oc * 32768;
        out[idx] += 2.0f * d;
    }
}

// ---------------- launch ----------------
extern "C" void kernel_launch(void* const* d_in, const int* in_sizes, int n_in,
                              void* d_out, int out_size)
{
    const float* x      = (const float*)d_in[0];
    const float* weight = (const float*)d_in[1];
    const float* bias   = (const float*)d_in[2];
    const float* lora_A = (const float*)d_in[3];
    const float* lora_B = (const float*)d_in[4];
    float* out = (float*)d_out;

    cudaFuncSetAttribute(conv_mma_kernel,
                         cudaFuncAttributeMaxDynamicSharedMemorySize, SMEM_TOTAL);
    cudaFuncSetAttribute(lora_fused_kernel,
                         cudaFuncAttributeMaxDynamicSharedMemorySize, LORA_SMEM);

    prep_kernel<<<2456, 256>>>(x, weight, lora_A);
    conv_mma_kernel<<<256, 768, SMEM_TOTAL>>>(bias, out);
    lora_fused_kernel<<<256, 1024, LORA_SMEM>>>(lora_B, out);
}